// round 12
// baseline (speedup 1.0000x reference)
#include <cuda_runtime.h>
#include <cstdint>

#define T_STEPS 2048
#define BATCH   64
#define H       256
#define HHALF   128
#define TBH     (T_STEPS * BATCH * H)
#define BH      (BATCH * H)

typedef unsigned long long u64;

// Scratch (no cudaMalloc allowed): xproj in CTA-local layout [128 CTAs][T][128].
__device__ float g_xproj[(size_t)TBH];

// ---------------------------------------------------------------------------
// helpers
// ---------------------------------------------------------------------------
__device__ __forceinline__ void fma2(u64& d, u64 a, u64 b)
{
    asm("fma.rn.f32x2 %0, %1, %2, %0;" : "+l"(d) : "l"(a), "l"(b));
}
__device__ __forceinline__ u64 add2(u64 a, u64 b)
{
    u64 r;
    asm("add.rn.f32x2 %0, %1, %2;" : "=l"(r) : "l"(a), "l"(b));
    return r;
}
__device__ __forceinline__ float fold2(u64 v)
{
    float lo, hi;
    asm("mov.b64 {%0, %1}, %2;" : "=f"(lo), "=f"(hi) : "l"(v));
    return lo + hi;
}
__device__ __forceinline__ uint32_t smem_u32(const void* p)
{
    uint32_t a;
    asm("{ .reg .u64 t; cvta.to.shared.u64 t, %1; cvt.u32.u64 %0, t; }"
        : "=r"(a) : "l"(p));
    return a;
}
__device__ __forceinline__ uint32_t mapa_u32(uint32_t la, uint32_t rank)
{
    uint32_t ra;
    asm("mapa.shared::cluster.u32 %0, %1, %2;" : "=r"(ra) : "r"(la), "r"(rank));
    return ra;
}
// tanh(x) = 1 - 2/(1+e^{2x}); rel err ~1e-6, graceful at large |x|.
__device__ __forceinline__ float fast_tanh(float x)
{
    float e = __expf(2.0f * x);
    return 1.0f - __fdividef(2.0f, 1.0f + e);
}

// ---------------------------------------------------------------------------
// THE kernel: xproj prelude + sequential scan, fused. 2-CTA cluster per
// batch row. Single launch -> ncu finally profiles THIS kernel.
// ---------------------------------------------------------------------------
__global__ void __cluster_dims__(2, 1, 1) __launch_bounds__(256, 1)
rnn_fused_kernel(const float* __restrict__ x, const float* __restrict__ hx,
                 const float* __restrict__ W_ih, const float* __restrict__ W_hh,
                 const float* __restrict__ b_ih, const float* __restrict__ b_hh,
                 float* __restrict__ out, float* __restrict__ hlast,
                 float* __restrict__ xproj)
{
    __shared__ __align__(16) u64   xs[8][HHALF];        // 8 t-rows of x pairs (8KB)
    __shared__ __align__(16) float part2[2][8][HHALF];  // k-half partials (8KB)
    __shared__ float bias_s[HHALF];
    __shared__ __align__(16) float h_s[2][HHALF];       // own-half h, by parity
    __shared__ __align__(16) u64   inbox[2][HHALF];     // (val, tag) from peer

    const int tid = threadIdx.x;
    uint32_t rank;
    asm("mov.u32 %0, %%cluster_ctarank;" : "=r"(rank));
    const int b   = blockIdx.x >> 1;
    const int j0  = (int)rank * HHALF;          // own j/k half base
    const int jp0 = (int)(rank ^ 1u) * HHALF;   // peer j half base

    const int  lj = tid & (HHALF - 1);
    const int  kh = tid >> 7;                   // k-half for the prelude

    // w[] holds W_ih[j0+lj, 128*kh ..) during the prelude, W_hh slice after.
    u64 w[64];

    // ======================= PRELUDE: xproj GEMM ===========================
    // xl[t][lj] = sum_i x[t,b,i]*W_ih[j0+lj,i] + b_ih + b_hh, CTA-local layout.
    float* const gx = xproj + (size_t)blockIdx.x * T_STEPS * HHALF;
    {
        const ulonglong2* Wr = reinterpret_cast<const ulonglong2*>(
            W_ih + (size_t)(j0 + lj) * H + HHALF * kh);
        #pragma unroll
        for (int q = 0; q < 32; q++) {
            ulonglong2 v = __ldg(&Wr[q]);
            w[2 * q]     = v.x;
            w[2 * q + 1] = v.y;
        }
        if (tid < HHALF)
            bias_s[tid] = __ldg(b_ih + j0 + tid) + __ldg(b_hh + j0 + tid);
        __syncthreads();

        float4* xsf = reinterpret_cast<float4*>(&xs[0][0]);
        for (int t0 = 0; t0 < T_STEPS; t0 += 8) {
            // stage x[t0..t0+8, b, :] (8KB): 512 float4, 2 per thread
            #pragma unroll
            for (int e = 0; e < 2; e++) {
                const int idx = e * 256 + tid;
                const int row = idx >> 6, c4 = idx & 63;
                xsf[idx] = *reinterpret_cast<const float4*>(
                    x + ((size_t)(t0 + row) * BATCH + b) * H + 4 * c4);
            }
            __syncthreads();

            #pragma unroll
            for (int tt = 0; tt < 8; tt++) {
                u64 a0 = 0ull, a1 = 0ull;
                const ulonglong2* xv = reinterpret_cast<const ulonglong2*>(
                    &xs[tt][kh * 64]);
                #pragma unroll
                for (int q = 0; q < 32; q++) {
                    ulonglong2 p = xv[q];
                    fma2(a0, p.x, w[2 * q]);
                    fma2(a1, p.y, w[2 * q + 1]);
                }
                part2[kh][tt][lj] = fold2(add2(a0, a1));
            }
            __syncthreads();

            // finalize 8*128 outputs, 4 per thread, coalesced local store
            #pragma unroll
            for (int e = 0; e < 4; e++) {
                const int idx = e * 256 + tid;
                const int tt = idx >> 7, l2 = idx & 127;
                gx[(size_t)(t0 + tt) * HHALF + l2] =
                    part2[0][tt][l2] + part2[1][tt][l2] + bias_s[l2];
            }
            __syncthreads();
        }
    }

    // ======================= SCAN (R11 structure) ==========================
    const bool sender = (tid >= HHALF);         // warps 4-7: peer-j dots
    const int  j      = sender ? (jp0 + lj) : (j0 + lj);

    // reload w[] with the W_hh slice: full own-half 128-k for my j column
    {
        const ulonglong2* Wr = reinterpret_cast<const ulonglong2*>(
            W_hh + (size_t)j * H + j0);
        #pragma unroll
        for (int q = 0; q < 32; q++) {
            ulonglong2 v = __ldg(&Wr[q]);
            w[2 * q]     = v.x;
            w[2 * q + 1] = v.y;
        }
    }

    // init h (own half) + inbox tags
    if (!sender) h_s[0][lj] = __ldg(hx + (size_t)b * H + j0 + lj);
    if (sender) {
        u64 inv;
        asm("mov.b64 %0, {%1, %2};" : "=l"(inv) : "f"(0.0f), "r"(0xFFFFFFFFu));
        inbox[0][lj] = inv;
        inbox[1][lj] = inv;
    }
    __syncthreads();
    asm volatile("barrier.cluster.arrive.aligned;" ::: "memory");
    asm volatile("barrier.cluster.wait.aligned;"   ::: "memory");

    const uint32_t inA = smem_u32(&inbox[0][lj]);  // + par*1024
    uint32_t peerIn = 0;
    if (sender) peerIn = mapa_u32(smem_u32(&inbox[0][lj]), rank ^ 1u);

    // xp prefetch, 2 deep (receivers only). PLAIN loads — g_xproj was written
    // in this kernel, __ldg (.CONSTANT) would be unsafe.
    const float* xpb = gx + lj;
    float xp0 = 0.0f, xp1 = 0.0f;
    if (!sender) {
        xp0 = xpb[0];
        xp1 = xpb[HHALF];
    }

    for (int t = 0; t < T_STEPS; t++) {
        const uint32_t par  = (uint32_t)t & 1u;
        const uint32_t ioff = par * (HHALF * 8);

        // full 128-k dot: 16 x (2 LDS.128 + 4 fma2), 4 chains
        u64 a0 = 0ull, a1 = 0ull, a2 = 0ull, a3 = 0ull;
        const ulonglong2* hp = reinterpret_cast<const ulonglong2*>(&h_s[par][0]);
        #pragma unroll
        for (int q = 0; q < 16; q++) {
            ulonglong2 u = hp[2 * q];
            ulonglong2 v = hp[2 * q + 1];
            fma2(a0, u.x, w[4 * q + 0]);
            fma2(a1, u.y, w[4 * q + 1]);
            fma2(a2, v.x, w[4 * q + 2]);
            fma2(a3, v.y, w[4 * q + 3]);
        }
        const float pj = fold2(add2(add2(a0, a1), add2(a2, a3)));

        if (sender) {
            u64 pv;
            asm("mov.b64 %0, {%1, %2};" : "=l"(pv) : "f"(pj), "r"((uint32_t)t));
            asm volatile("st.shared::cluster.b64 [%0], %1;"
                         :: "r"(peerIn + ioff), "l"(pv) : "memory");
        } else {
            float rv;
            {
                const uint32_t pa = inA + ioff;
                uint32_t lo, hi;
                do {
                    asm volatile("ld.volatile.shared.v2.u32 {%0, %1}, [%2];"
                                 : "=r"(lo), "=r"(hi) : "r"(pa) : "memory");
                } while (hi != (uint32_t)t);
                rv = __uint_as_float(lo);
            }
            const float hn = fast_tanh(pj + rv + xp0);
            h_s[par ^ 1u][lj] = hn;
            out[(size_t)t * BH + (size_t)b * H + j0 + lj] = hn;
            if (hlast && t == T_STEPS - 1)
                hlast[(size_t)b * H + j0 + lj] = hn;
            xp0 = xp1;
            if (t + 2 < T_STEPS)
                xp1 = xpb[(size_t)(t + 2) * HHALF];
        }
        __syncthreads();   // h_s[par^1] complete; inbox[par] reusable at t+2
    }

    // Drain before retiring (R2 lesson: peer remote stores may be in flight).
    asm volatile("barrier.cluster.arrive.aligned;" ::: "memory");
    asm volatile("barrier.cluster.wait.aligned;"   ::: "memory");
}

// ---------------------------------------------------------------------------
extern "C" void kernel_launch(void* const* d_in, const int* in_sizes, int n_in,
                              void* d_out, int out_size)
{
    const float* x    = (const float*)d_in[0];   // [T,B,256]
    const float* hx   = (const float*)d_in[1];   // [B,256]
    const float* W_ih = (const float*)d_in[2];   // [256,256]
    const float* W_hh = (const float*)d_in[3];   // [256,256]
    const float* b_ih = (const float*)d_in[4];   // [256]
    const float* b_hh = (const float*)d_in[5];   // [256]
    float* out = (float*)d_out;

    float* d_xproj;
    cudaGetSymbolAddress((void**)&d_xproj, g_xproj);

    float* hlast = (out_size >= TBH + BATCH * H) ? (out + TBH) : nullptr;

    rnn_fused_kernel<<<2 * BATCH, 256>>>(x, hx, W_ih, W_hh, b_ih, b_hh,
                                         out, hlast, d_xproj);
    (void)in_sizes; (void)n_in;
}

// round 13
// speedup vs baseline: 1.1058x; 1.1058x over previous
#include <cuda_runtime.h>
#include <cstdint>

#define T_STEPS 2048
#define BATCH   64
#define H       256
#define HHALF   128
#define TBH     (T_STEPS * BATCH * H)
#define BH      (BATCH * H)

typedef unsigned long long u64;

// Scratch (no cudaMalloc allowed): packed W_ih and precomputed xproj.
__device__ u64   g_Wp[(H / 2) * H];      // Wp[u][c] = pack(W_ih[c][2u], W_ih[c][2u+1])
__device__ float g_xproj[(size_t)TBH];   // [T*B][H]

// ---------------------------------------------------------------------------
// helpers
// ---------------------------------------------------------------------------
__device__ __forceinline__ void fma2(u64& d, u64 a, u64 b)
{
    asm("fma.rn.f32x2 %0, %1, %2, %0;" : "+l"(d) : "l"(a), "l"(b));
}
__device__ __forceinline__ u64 add2(u64 a, u64 b)
{
    u64 r;
    asm("add.rn.f32x2 %0, %1, %2;" : "=l"(r) : "l"(a), "l"(b));
    return r;
}
__device__ __forceinline__ float fold2(u64 v)
{
    float lo, hi;
    asm("mov.b64 {%0, %1}, %2;" : "=f"(lo), "=f"(hi) : "l"(v));
    return lo + hi;
}
__device__ __forceinline__ uint32_t smem_u32(const void* p)
{
    uint32_t a;
    asm("{ .reg .u64 t; cvta.to.shared.u64 t, %1; cvt.u32.u64 %0, t; }"
        : "=r"(a) : "l"(p));
    return a;
}
__device__ __forceinline__ uint32_t mapa_u32(uint32_t la, uint32_t rank)
{
    uint32_t ra;
    asm("mapa.shared::cluster.u32 %0, %1, %2;" : "=r"(ra) : "r"(la), "r"(rank));
    return ra;
}
__device__ __forceinline__ float shfl_bfly16(float v)
{
    float r;
    asm("shfl.sync.bfly.b32 %0, %1, 16, 0x1F, 0xFFFFFFFF;" : "=f"(r) : "f"(v));
    return r;
}
// tanh(x) = 1 - 2/(1+e^{2x}); rel err ~1e-6, graceful at large |x|.
__device__ __forceinline__ float fast_tanh(float x)
{
    float e = __expf(2.0f * x);
    return 1.0f - __fdividef(2.0f, 1.0f + e);
}

// ---------------------------------------------------------------------------
// Kernel 1: pack W_ih into pair layout (u64 transpose).
// ---------------------------------------------------------------------------
__global__ void pack_wih_kernel(const float* __restrict__ W, u64* __restrict__ Wp)
{
    __shared__ u64 tile[32][33];
    const int u0 = (blockIdx.x & 3) * 32;
    const int c0 = (blockIdx.x >> 2) * 32;
    const u64* ullW = reinterpret_cast<const u64*>(W);
    tile[threadIdx.y][threadIdx.x] = ullW[(c0 + threadIdx.y) * (H / 2) + (u0 + threadIdx.x)];
    __syncthreads();
    Wp[(u0 + threadIdx.y) * H + (c0 + threadIdx.x)] = tile[threadIdx.x][threadIdx.y];
}

// ---------------------------------------------------------------------------
// Kernel 2: xproj (256 thr, 4 rows x 8 strided cols, f32x2) — R7 version.
// ---------------------------------------------------------------------------
__global__ __launch_bounds__(256, 2)
void xproj_kernel(const float* __restrict__ x, const u64* __restrict__ Wp,
                  const float* __restrict__ b_ih, const float* __restrict__ b_hh,
                  float* __restrict__ xproj)
{
    __shared__ __align__(16) u64 xs[32][H / 2];

    const int tid = threadIdx.x;
    const size_t row0 = (size_t)blockIdx.x * 32;

    const float4* xg = reinterpret_cast<const float4*>(x + row0 * H);
    float4* xsf = reinterpret_cast<float4*>(&xs[0][0]);
    #pragma unroll
    for (int i = 0; i < 8; i++) xsf[tid + i * 256] = xg[tid + i * 256];
    __syncthreads();

    const int lane = tid & 31;
    const int rg   = tid >> 5;
    const int m0   = 4 * rg;

    u64 acc[4][8];
    #pragma unroll
    for (int m = 0; m < 4; m++)
        #pragma unroll
        for (int i = 0; i < 8; i++) acc[m][i] = 0ull;

    #pragma unroll 2
    for (int u = 0; u < H / 2; u++) {
        u64 w[8];
        #pragma unroll
        for (int i = 0; i < 8; i++) w[i] = __ldg(&Wp[u * H + lane + 32 * i]);
        #pragma unroll
        for (int m = 0; m < 4; m++) {
            u64 xv = xs[m0 + m][u];
            #pragma unroll
            for (int i = 0; i < 8; i++) fma2(acc[m][i], xv, w[i]);
        }
    }

    #pragma unroll
    for (int m = 0; m < 4; m++) {
        #pragma unroll
        for (int i = 0; i < 8; i++) {
            const int c = lane + 32 * i;
            float v = fold2(acc[m][i]) + b_ih[c] + b_hh[c];
            xproj[(row0 + m0 + m) * H + c] = v;
        }
    }
}

// ---------------------------------------------------------------------------
// Kernel 3: scan, 2-CTA cluster per batch row, partial-exchange topology,
// 512 threads: 2 threads per j-column (k-half split, shfl.bfly(16) combine).
// Warps 0-7 receivers (own-half j), warps 8-15 senders (peer-half j).
// ---------------------------------------------------------------------------
__global__ void __cluster_dims__(2, 1, 1) __launch_bounds__(512, 1)
rnn_scan_kernel(const float* __restrict__ xproj, const float* __restrict__ hx,
                const float* __restrict__ W_hh, float* __restrict__ out,
                float* __restrict__ hlast)
{
    __shared__ __align__(16) float h_s[2][HHALF];   // own-half h, by parity
    __shared__ __align__(16) u64 inbox[2][HHALF];   // (val, tag) from peer

    const int tid  = threadIdx.x;
    const int wrp  = tid >> 5;
    const int lane = tid & 31;
    uint32_t rank;
    asm("mov.u32 %0, %%cluster_ctarank;" : "=r"(rank));
    const int b   = blockIdx.x >> 1;
    const int j0  = (int)rank * HHALF;          // own j/k half base
    const int jp0 = (int)(rank ^ 1u) * HHALF;   // peer j half base

    const bool sender = (wrp >= 8);             // warps 8-15: peer-j dots
    const int  jslot  = (wrp & 7) * 16 + (lane & 15);   // [0,128)
    const int  khalf  = lane >> 4;              // which 64-k half of own half
    const int  j      = sender ? (jp0 + jslot) : (j0 + jslot);
    const bool head   = (lane < 16);            // owns the j tail work

    // --- weights: my 64-k chunk of own half for column j (32 pairs)
    u64 w[32];
    {
        const ulonglong2* Wr = reinterpret_cast<const ulonglong2*>(
            W_hh + (size_t)j * H + j0 + 64 * khalf);
        #pragma unroll
        for (int q = 0; q < 16; q++) {
            ulonglong2 v = __ldg(&Wr[q]);
            w[2 * q]     = v.x;
            w[2 * q + 1] = v.y;
        }
    }

    // --- init h (own half) + inbox tags
    if (tid < HHALF) {
        h_s[0][tid] = __ldg(hx + (size_t)b * H + j0 + tid);
    } else if (tid < 2 * HHALF) {
        u64 inv;
        asm("mov.b64 %0, {%1, %2};" : "=l"(inv) : "f"(0.0f), "r"(0xFFFFFFFFu));
        inbox[0][tid - HHALF] = inv;
        inbox[1][tid - HHALF] = inv;
    }
    __syncthreads();
    asm volatile("barrier.cluster.arrive.aligned;" ::: "memory");
    asm volatile("barrier.cluster.wait.aligned;"   ::: "memory");

    // --- addresses
    const uint32_t inA = smem_u32(&inbox[0][jslot]);   // + par*1024
    uint32_t peerIn = 0;
    if (sender && head) peerIn = mapa_u32(inA, rank ^ 1u);

    // xp prefetch, 2 deep (receiver heads only)
    const float* xpb = xproj + (size_t)b * H + j0 + jslot;
    float xp0 = 0.0f, xp1 = 0.0f;
    if (!sender && head) {
        xp0 = __ldg(xpb);
        xp1 = __ldg(xpb + BH);
    }

    for (int t = 0; t < T_STEPS; t++) {
        const uint32_t par  = (uint32_t)t & 1u;
        const uint32_t ioff = par * (HHALF * 8);

        // --- 64-k half-dot: 8 x (2 LDS.128 + 4 fma2), 4 chains
        u64 a0 = 0ull, a1 = 0ull, a2 = 0ull, a3 = 0ull;
        const ulonglong2* hp = reinterpret_cast<const ulonglong2*>(
            &h_s[par][64 * khalf]);
        #pragma unroll
        for (int q = 0; q < 8; q++) {
            ulonglong2 u = hp[2 * q];        // k-off: 8q .. 8q+3
            ulonglong2 v = hp[2 * q + 1];    // k-off: 8q+4 .. 8q+7
            fma2(a0, u.x, w[4 * q + 0]);
            fma2(a1, u.y, w[4 * q + 1]);
            fma2(a2, v.x, w[4 * q + 2]);
            fma2(a3, v.y, w[4 * q + 3]);
        }
        float pj = fold2(add2(add2(a0, a1), add2(a2, a3)));
        pj += shfl_bfly16(pj);               // combine the two k-halves

        if (sender) {
            if (head) {
                u64 pv;
                asm("mov.b64 %0, {%1, %2};" : "=l"(pv) : "f"(pj), "r"((uint32_t)t));
                asm volatile("st.shared::cluster.b64 [%0], %1;"
                             :: "r"(peerIn + ioff), "l"(pv) : "memory");
            }
        } else if (head) {
            // poll my inbox word for this step's tag
            float rv;
            {
                const uint32_t pa = inA + ioff;
                uint32_t lo, hi;
                do {
                    asm volatile("ld.volatile.shared.v2.u32 {%0, %1}, [%2];"
                                 : "=r"(lo), "=r"(hi) : "r"(pa) : "memory");
                } while (hi != (uint32_t)t);
                rv = __uint_as_float(lo);
            }
            const float hn = fast_tanh(pj + rv + xp0);
            h_s[par ^ 1u][jslot] = hn;
            out[(size_t)t * BH + (size_t)b * H + j0 + jslot] = hn;
            if (hlast && t == T_STEPS - 1)
                hlast[(size_t)b * H + j0 + jslot] = hn;
            xp0 = xp1;
            if (t + 2 < T_STEPS)
                xp1 = __ldg(xpb + (size_t)(t + 2) * BH);
        }
        __syncthreads();   // h_s[par^1] complete; inbox[par] reusable at t+2
    }

    // Drain before retiring (R2 lesson: peer remote stores may be in flight).
    asm volatile("barrier.cluster.arrive.aligned;" ::: "memory");
    asm volatile("barrier.cluster.wait.aligned;"   ::: "memory");
}

// ---------------------------------------------------------------------------
extern "C" void kernel_launch(void* const* d_in, const int* in_sizes, int n_in,
                              void* d_out, int out_size)
{
    const float* x    = (const float*)d_in[0];   // [T,B,256]
    const float* hx   = (const float*)d_in[1];   // [B,256]
    const float* W_ih = (const float*)d_in[2];   // [256,256]
    const float* W_hh = (const float*)d_in[3];   // [256,256]
    const float* b_ih = (const float*)d_in[4];   // [256]
    const float* b_hh = (const float*)d_in[5];   // [256]
    float* out = (float*)d_out;

    u64*   d_Wp;
    float* d_xproj;
    cudaGetSymbolAddress((void**)&d_Wp, g_Wp);
    cudaGetSymbolAddress((void**)&d_xproj, g_xproj);

    float* hlast = (out_size >= TBH + BATCH * H) ? (out + TBH) : nullptr;

    pack_wih_kernel<<<32, dim3(32, 32)>>>(W_ih, d_Wp);
    xproj_kernel<<<(T_STEPS * BATCH) / 32, 256>>>(x, d_Wp, b_ih, b_hh, d_xproj);
    rnn_scan_kernel<<<2 * BATCH, 512>>>(d_xproj, hx, W_hh, out, hlast);
    (void)in_sizes; (void)n_in;
}

// round 14
// speedup vs baseline: 1.5779x; 1.4269x over previous
#include <cuda_runtime.h>
#include <cstdint>

#define T_STEPS 2048
#define BATCH   64
#define H       256
#define HHALF   128
#define TBH     (T_STEPS * BATCH * H)
#define BH      (BATCH * H)

typedef unsigned long long u64;

// Scratch (no cudaMalloc allowed): packed W_ih and precomputed xproj.
__device__ u64   g_Wp[(H / 2) * H];      // Wp[u][c] = pack(W_ih[c][2u], W_ih[c][2u+1])
__device__ float g_xproj[(size_t)TBH];   // [T*B][H]

// ---------------------------------------------------------------------------
// helpers
// ---------------------------------------------------------------------------
__device__ __forceinline__ void fma2(u64& d, u64 a, u64 b)
{
    asm("fma.rn.f32x2 %0, %1, %2, %0;" : "+l"(d) : "l"(a), "l"(b));
}
__device__ __forceinline__ u64 add2(u64 a, u64 b)
{
    u64 r;
    asm("add.rn.f32x2 %0, %1, %2;" : "=l"(r) : "l"(a), "l"(b));
    return r;
}
__device__ __forceinline__ float fold2(u64 v)
{
    float lo, hi;
    asm("mov.b64 {%0, %1}, %2;" : "=f"(lo), "=f"(hi) : "l"(v));
    return lo + hi;
}
__device__ __forceinline__ uint32_t smem_u32(const void* p)
{
    uint32_t a;
    asm("{ .reg .u64 t; cvta.to.shared.u64 t, %1; cvt.u32.u64 %0, t; }"
        : "=r"(a) : "l"(p));
    return a;
}
__device__ __forceinline__ uint32_t mapa_u32(uint32_t la, uint32_t rank)
{
    uint32_t ra;
    asm("mapa.shared::cluster.u32 %0, %1, %2;" : "=r"(ra) : "r"(la), "r"(rank));
    return ra;
}
// tanh(x) = 1 - 2/(1+e^{2x}); rel err ~1e-6, graceful at large |x|.
__device__ __forceinline__ float fast_tanh(float x)
{
    float e = __expf(2.0f * x);
    return 1.0f - __fdividef(2.0f, 1.0f + e);
}

// ---------------------------------------------------------------------------
// Kernel 1: pack W_ih into pair layout (u64 transpose).
// ---------------------------------------------------------------------------
__global__ void pack_wih_kernel(const float* __restrict__ W, u64* __restrict__ Wp)
{
    __shared__ u64 tile[32][33];
    const int u0 = (blockIdx.x & 3) * 32;
    const int c0 = (blockIdx.x >> 2) * 32;
    const u64* ullW = reinterpret_cast<const u64*>(W);
    tile[threadIdx.y][threadIdx.x] = ullW[(c0 + threadIdx.y) * (H / 2) + (u0 + threadIdx.x)];
    __syncthreads();
    Wp[(u0 + threadIdx.y) * H + (c0 + threadIdx.x)] = tile[threadIdx.x][threadIdx.y];
}

// ---------------------------------------------------------------------------
// Kernel 2: xproj (256 thr, 4 rows x 8 strided cols, f32x2) — R7 version.
// ---------------------------------------------------------------------------
__global__ __launch_bounds__(256, 2)
void xproj_kernel(const float* __restrict__ x, const u64* __restrict__ Wp,
                  const float* __restrict__ b_ih, const float* __restrict__ b_hh,
                  float* __restrict__ xproj)
{
    __shared__ __align__(16) u64 xs[32][H / 2];

    const int tid = threadIdx.x;
    const size_t row0 = (size_t)blockIdx.x * 32;

    const float4* xg = reinterpret_cast<const float4*>(x + row0 * H);
    float4* xsf = reinterpret_cast<float4*>(&xs[0][0]);
    #pragma unroll
    for (int i = 0; i < 8; i++) xsf[tid + i * 256] = xg[tid + i * 256];
    __syncthreads();

    const int lane = tid & 31;
    const int rg   = tid >> 5;
    const int m0   = 4 * rg;

    u64 acc[4][8];
    #pragma unroll
    for (int m = 0; m < 4; m++)
        #pragma unroll
        for (int i = 0; i < 8; i++) acc[m][i] = 0ull;

    #pragma unroll 2
    for (int u = 0; u < H / 2; u++) {
        u64 w[8];
        #pragma unroll
        for (int i = 0; i < 8; i++) w[i] = __ldg(&Wp[u * H + lane + 32 * i]);
        #pragma unroll
        for (int m = 0; m < 4; m++) {
            u64 xv = xs[m0 + m][u];
            #pragma unroll
            for (int i = 0; i < 8; i++) fma2(acc[m][i], xv, w[i]);
        }
    }

    #pragma unroll
    for (int m = 0; m < 4; m++) {
        #pragma unroll
        for (int i = 0; i < 8; i++) {
            const int c = lane + 32 * i;
            float v = fold2(acc[m][i]) + b_ih[c] + b_hh[c];
            xproj[(row0 + m0 + m) * H + c] = v;
        }
    }
}

// ---------------------------------------------------------------------------
// Kernel 3: scan, 2-CTA cluster per batch row, partial-exchange topology
// (R7 skeleton, 256 thr). Lean LDS.128 dot (R11, verified). Receiver's
// pre-barrier tail minimized: poll -> tanh -> STS -> bar; out STG and xp
// prefetch issue AFTER the barrier (off the inter-CTA critical cycle).
// ---------------------------------------------------------------------------
__global__ void __cluster_dims__(2, 1, 1) __launch_bounds__(256, 1)
rnn_scan_kernel(const float* __restrict__ xproj, const float* __restrict__ hx,
                const float* __restrict__ W_hh, float* __restrict__ out,
                float* __restrict__ hlast)
{
    __shared__ __align__(16) float h_s[2][HHALF];   // own-half h, by parity
    __shared__ __align__(16) u64 inbox[2][HHALF];   // (val, tag) from peer

    const int tid = threadIdx.x;
    uint32_t rank;
    asm("mov.u32 %0, %%cluster_ctarank;" : "=r"(rank));
    const int b   = blockIdx.x >> 1;
    const int j0  = (int)rank * HHALF;          // own j/k half base
    const int jp0 = (int)(rank ^ 1u) * HHALF;   // peer j half base

    const bool sender = (tid >= HHALF);         // warps 4-7: peer-j dots
    const int  lj     = tid & (HHALF - 1);
    const int  j      = sender ? (jp0 + lj) : (j0 + lj);

    // --- weights: full 128-k chunk (own half) for my single j column
    u64 w[64];
    {
        const ulonglong2* Wr = reinterpret_cast<const ulonglong2*>(
            W_hh + (size_t)j * H + j0);
        #pragma unroll
        for (int q = 0; q < 32; q++) {
            ulonglong2 v = __ldg(&Wr[q]);
            w[2 * q]     = v.x;
            w[2 * q + 1] = v.y;
        }
    }

    // --- init h (own half) + inbox tags
    if (!sender) h_s[0][lj] = __ldg(hx + (size_t)b * H + j0 + lj);
    if (sender) {
        u64 inv;
        asm("mov.b64 %0, {%1, %2};" : "=l"(inv) : "f"(0.0f), "r"(0xFFFFFFFFu));
        inbox[0][lj] = inv;
        inbox[1][lj] = inv;
    }
    __syncthreads();
    asm volatile("barrier.cluster.arrive.aligned;" ::: "memory");
    asm volatile("barrier.cluster.wait.aligned;"   ::: "memory");

    // --- addresses
    const uint32_t inA = smem_u32(&inbox[0][lj]);  // + par*1024
    uint32_t peerIn = 0;
    if (sender) peerIn = mapa_u32(smem_u32(&inbox[0][lj]), rank ^ 1u);

    // xp prefetch, 2 deep (receivers only)
    const float* xpb = xproj + (size_t)b * H + j0 + lj;
    float xp0 = 0.0f, xp1 = 0.0f;
    if (!sender) {
        xp0 = __ldg(xpb);
        xp1 = __ldg(xpb + BH);
    }

    float hn = 0.0f;   // receiver's last produced h (for hlast after loop)

    for (int t = 0; t < T_STEPS; t++) {
        const uint32_t par  = (uint32_t)t & 1u;
        const uint32_t ioff = par * (HHALF * 8);

        // --- full 128-k dot: 16 x (2 LDS.128 + 4 fma2), 4 chains, no MOVs
        u64 a0 = 0ull, a1 = 0ull, a2 = 0ull, a3 = 0ull;
        const ulonglong2* hp = reinterpret_cast<const ulonglong2*>(&h_s[par][0]);
        #pragma unroll
        for (int q = 0; q < 16; q++) {
            ulonglong2 u = hp[2 * q];        // k: 8q   .. 8q+3
            ulonglong2 v = hp[2 * q + 1];    // k: 8q+4 .. 8q+7
            fma2(a0, u.x, w[4 * q + 0]);
            fma2(a1, u.y, w[4 * q + 1]);
            fma2(a2, v.x, w[4 * q + 2]);
            fma2(a3, v.y, w[4 * q + 3]);
        }
        const float pj = fold2(add2(add2(a0, a1), add2(a2, a3)));

        if (sender) {
            // fire tagged partial into peer's inbox ASAP
            u64 pv;
            asm("mov.b64 %0, {%1, %2};" : "=l"(pv) : "f"(pj), "r"((uint32_t)t));
            asm volatile("st.shared::cluster.b64 [%0], %1;"
                         :: "r"(peerIn + ioff), "l"(pv) : "memory");
        } else {
            // poll my inbox word for this step's tag
            float rv;
            {
                const uint32_t pa = inA + ioff;
                uint32_t lo, hi;
                do {
                    asm volatile("ld.volatile.shared.v2.u32 {%0, %1}, [%2];"
                                 : "=r"(lo), "=r"(hi) : "r"(pa) : "memory");
                } while (hi != (uint32_t)t);
                rv = __uint_as_float(lo);
            }
            hn = fast_tanh(pj + rv + xp0);
            h_s[par ^ 1u][lj] = hn;          // ONLY critical store before bar
        }
        __syncthreads();   // h_s[par^1] complete; inbox[par] reusable at t+2

        if (!sender) {
            // off-cycle work: out store + xp rotate/prefetch
            out[(size_t)t * BH + (size_t)b * H + j0 + lj] = hn;
            xp0 = xp1;
            if (t + 2 < T_STEPS)
                xp1 = __ldg(xpb + (size_t)(t + 2) * BH);
        }
    }

    if (!sender && hlast)
        hlast[(size_t)b * H + j0 + lj] = hn;

    // Drain before retiring (R2 lesson: peer remote stores may be in flight).
    asm volatile("barrier.cluster.arrive.aligned;" ::: "memory");
    asm volatile("barrier.cluster.wait.aligned;"   ::: "memory");
}

// ---------------------------------------------------------------------------
extern "C" void kernel_launch(void* const* d_in, const int* in_sizes, int n_in,
                              void* d_out, int out_size)
{
    const float* x    = (const float*)d_in[0];   // [T,B,256]
    const float* hx   = (const float*)d_in[1];   // [B,256]
    const float* W_ih = (const float*)d_in[2];   // [256,256]
    const float* W_hh = (const float*)d_in[3];   // [256,256]
    const float* b_ih = (const float*)d_in[4];   // [256]
    const float* b_hh = (const float*)d_in[5];   // [256]
    float* out = (float*)d_out;

    u64*   d_Wp;
    float* d_xproj;
    cudaGetSymbolAddress((void**)&d_Wp, g_Wp);
    cudaGetSymbolAddress((void**)&d_xproj, g_xproj);

    float* hlast = (out_size >= TBH + BATCH * H) ? (out + TBH) : nullptr;

    pack_wih_kernel<<<32, dim3(32, 32)>>>(W_ih, d_Wp);
    xproj_kernel<<<(T_STEPS * BATCH) / 32, 256>>>(x, d_Wp, b_ih, b_hh, d_xproj);
    rnn_scan_kernel<<<2 * BATCH, 256>>>(d_xproj, hx, W_hh, out, hlast);
    (void)in_sizes; (void)n_in;
}